// round 12
// baseline (speedup 1.0000x reference)
#include <cuda_runtime.h>
#include <cuda_fp16.h>
#include <mma.h>
#include <cstdint>

using namespace nvcuda;

#define BB   32
#define TT   512
#define DD   256
#define FF   256
#define MEL  2304
#define EPSF 1e-5f

#define TPB    256      // 8 warps -> 2 blocks/SM
#define NCHUNK 24       // K=768 in chunks of 32
#define MTILE  64       // tokens per block
#define NTILES 8        // tiles per batch -> 256 blocks

// ---------------- device scratch ----------------
__device__ __align__(128) __half g_xpad [(size_t)BB*(TT+2)*DD];
__device__ __align__(128) __half g_h1   [(size_t)BB*(TT+2)*FF];
__device__ __align__(128) __half g_wB   [2*768*256];              // [stage][kcol][f]
__device__ int g_idx[BB*MEL];

// ---------------- conv smem layout (bytes) ----------------
// stage: A 64x40 fp16 (5120) + B 32x264 fp16 (16896) = 22016; 3 stages = 66048
// C 64x264 f32 = 67584 @0 (overlaps stages after MMA); par @67584 (4096)
#define STAGE_BYTES 22016
#define OFF_B    5120
#define OFF_PAR  67584
#define SMEM_BYTES 71680
#define A_STRIDE 40
#define B_STRIDE 264
#define C_STRIDE 264

__device__ __forceinline__ uint32_t smem_u32(const void* p) {
    uint32_t a;
    asm("{ .reg .u64 t; cvta.to.shared.u64 t, %1; cvt.u32.u64 %0, t; }" : "=r"(a) : "l"(p));
    return a;
}
__device__ __forceinline__ void cp16(uint32_t dst, const void* src) {
    asm volatile("cp.async.cg.shared.global [%0], [%1], 16;" :: "r"(dst), "l"(src));
}
__device__ __forceinline__ void cp_commit() { asm volatile("cp.async.commit_group;" ::: "memory"); }
template<int N> __device__ __forceinline__ void cp_wait() { asm volatile("cp.async.wait_group %0;" :: "n"(N) : "memory"); }

// ---------------- cum_idx ----------------
__global__ __launch_bounds__(512)
void cum_idx(const int* __restrict__ target) {
    __shared__ int cs[TT];
    __shared__ int wsum[16];
    const int b = blockIdx.x, t = threadIdx.x;
    const int wid = t >> 5, lid = t & 31;
    int sc = target[b*TT + t];
    #pragma unroll
    for (int o = 1; o < 32; o <<= 1) {
        int n = __shfl_up_sync(0xffffffffu, sc, o);
        if (lid >= o) sc += n;
    }
    if (lid == 31) wsum[wid] = sc;
    __syncthreads();
    if (wid == 0 && lid < 16) {
        int w = wsum[lid];
        #pragma unroll
        for (int o = 1; o < 16; o <<= 1) {
            int n = __shfl_up_sync(0xffffu, w, o);
            if (lid >= o) w += n;
        }
        wsum[lid] = w;
    }
    __syncthreads();
    cs[t] = sc + (wid ? wsum[wid-1] : 0);
    __syncthreads();
    const int total = cs[TT-1];
    for (int to = t; to < MEL; to += TT) {
        int lo = 0, hi = TT;
        while (lo < hi) {
            int mid = (lo + hi) >> 1;
            if (cs[mid] <= to) lo = mid + 1; else hi = mid;
        }
        g_idx[b*MEL + to] = (to < total) ? min(lo, TT-1) : -1;
    }
}

// ---------------- prep_xw ----------------
#define PW_PITCH 778
#define PREP_SMEM (32*PW_PITCH*2)
#define NXBLK 516
#define NTOTX (BB*(TT+2)*DD)

__global__ __launch_bounds__(512)
void prep_xw(const float* __restrict__ x,
             const float* __restrict__ w1,
             const float* __restrict__ w2) {
    extern __shared__ char dsm[];
    const int j   = blockIdx.x;
    const int tid = threadIdx.x;
    const int wid = tid >> 5, lane = tid & 31;

    if (j < 16) {
        const int stg   = j >> 3;
        const int f0    = (j & 7) * 32;
        const float* w  = stg ? w2 : w1;
        __half* S = (__half*)dsm;
        #pragma unroll
        for (int it = 0; it < 12; ++it) {
            int u  = tid + it*512;
            int r  = u / 192;
            int m  = (u % 192) * 4;
            float4 v = __ldg((const float4*)(w + (size_t)(f0 + r)*768 + m));
            __half* dst = S + r*PW_PITCH + m;
            dst[0] = __float2half(v.x);
            dst[1] = __float2half(v.y);
            dst[2] = __float2half(v.z);
            dst[3] = __float2half(v.w);
        }
        __syncthreads();
        for (int i = 0; i < 48; ++i) {
            int kcol = wid*48 + i;
            int k = kcol >> 8, d = kcol & 255;
            int m = d*3 + k;
            g_wB[((size_t)(stg*768 + kcol))*256 + f0 + lane] = S[lane*PW_PITCH + m];
        }
    } else {
        const int bb = j - 16;
        #pragma unroll
        for (int it = 0; it < 16; ++it) {
            int i = (bb*16 + it)*512 + tid;
            if (i < NTOTX) {
                int d   = i & (DD-1);
                int row = i >> 8;
                int t   = row % (TT+2);
                int b   = row / (TT+2);
                float v = (t == 0 || t == TT+1) ? 0.f : x[((size_t)(b*TT + t - 1))*DD + d];
                g_xpad[i] = __float2half(v);
            }
        }
        if (bb == 0) {
            #pragma unroll
            for (int it = 0; it < 32; ++it) {
                int i = it*512 + tid;
                int d = i & (FF-1);
                int r = i >> 8;
                int b = r >> 1;
                int t = (r & 1) ? (TT+1) : 0;
                g_h1[((size_t)(b*(TT+2) + t))*FF + d] = __float2half(0.f);
            }
        }
    }
}

// ---------------- fused conv: 2 blocks/SM, 8 warps each ----------------
template<int STAGE>
__global__ __launch_bounds__(TPB, 2)
void conv_wmma(const float* __restrict__ bias,
               const float* __restrict__ gamma,
               const float* __restrict__ beta,
               const float* __restrict__ lin_w,
               const float* __restrict__ lin_b,
               float* __restrict__ dur_out) {
    extern __shared__ char smem[];
    const uint32_t sbase = smem_u32(smem);
    const int tid  = threadIdx.x;
    const int wid  = tid >> 5;
    const int lane = tid & 31;
    const int b    = blockIdx.x >> 3;
    const int t0   = (blockIdx.x & 7) * MTILE;

    const __half* __restrict__ srcA = STAGE ? g_h1 : g_xpad;
    float* Cs  = (float*)smem;
    float* par = (float*)(smem + OFF_PAR);

    par[tid]       = bias [tid];
    par[256 + tid] = gamma[tid];
    par[512 + tid] = beta [tid];
    par[768 + tid] = STAGE ? lin_w[tid] : 0.f;

    auto load_chunk = [&](int c) {
        const uint32_t st = sbase + (uint32_t)(c % 3) * STAGE_BYTES;
        const int k   = c >> 3;
        const int d0  = (c & 7) * 32;
        // A: 64 rows x 4 segs = 256 cp16, one per thread
        {
            int r = tid >> 2, seg = tid & 3;
            size_t go = ((size_t)(b*(TT+2) + t0 + k + r))*DD + d0 + seg*8;
            cp16(st + r*(A_STRIDE*2) + seg*16, srcA + go);
        }
        // B: 32 rows x 32 segs = 1024 cp16
        {
            const size_t bbase = ((size_t)(STAGE*768 + c*32))*256;
            #pragma unroll
            for (int it = 0; it < 4; ++it) {
                int u = tid + it*TPB;
                int r = u >> 5, seg = u & 31;
                cp16(st + OFF_B + r*(B_STRIDE*2) + seg*16, g_wB + bbase + (size_t)r*256 + seg*8);
            }
        }
        cp_commit();
    };

    // warp tile: 32 tokens x 64 channels; 2 warps (M) x 4 warps (N)
    const int wm = wid & 1;
    const int wn = wid >> 1;

    wmma::fragment<wmma::accumulator, 16, 16, 16, float> acc[2][4];
    #pragma unroll
    for (int i = 0; i < 2; ++i)
        #pragma unroll
        for (int j = 0; j < 4; ++j)
            wmma::fill_fragment(acc[i][j], 0.f);

    load_chunk(0);
    load_chunk(1);

    for (int c = 0; c < NCHUNK; ++c) {
        if (c < NCHUNK - 1) cp_wait<1>(); else cp_wait<0>();
        __syncthreads();
        const char* stg = smem + (size_t)(c % 3) * STAGE_BYTES;
        const __half* As = (const __half*)(stg);
        const __half* Bs = (const __half*)(stg + OFF_B);
        #pragma unroll
        for (int ks = 0; ks < 2; ++ks) {
            wmma::fragment<wmma::matrix_a, 16, 16, 16, __half, wmma::row_major> af[2];
            #pragma unroll
            for (int i = 0; i < 2; ++i)
                wmma::load_matrix_sync(af[i], As + (wm*32 + i*16)*A_STRIDE + ks*16, A_STRIDE);
            #pragma unroll
            for (int j = 0; j < 4; ++j) {
                wmma::fragment<wmma::matrix_b, 16, 16, 16, __half, wmma::row_major> bf;
                wmma::load_matrix_sync(bf, Bs + (ks*16)*B_STRIDE + wn*64 + j*16, B_STRIDE);
                #pragma unroll
                for (int i = 0; i < 2; ++i)
                    wmma::mma_sync(acc[i][j], af[i], bf, acc[i][j]);
            }
        }
        if (c + 2 < NCHUNK) load_chunk(c + 2);
    }

    __syncthreads();
    #pragma unroll
    for (int i = 0; i < 2; ++i)
        #pragma unroll
        for (int j = 0; j < 4; ++j)
            wmma::store_matrix_sync(Cs + (size_t)(wm*32 + i*16)*C_STRIDE + wn*64 + j*16,
                                    acc[i][j], C_STRIDE, wmma::mem_row_major);
    __syncthreads();

    // epilogue: 8 warps x 8 rows = 64 token rows
    #pragma unroll
    for (int rr = 0; rr < 8; ++rr) {
        const int row = wid*8 + rr;
        float v[8];
        float s = 0.f, ss = 0.f;
        #pragma unroll
        for (int j = 0; j < 8; ++j) {
            v[j] = Cs[(size_t)row*C_STRIDE + lane + j*32] + par[lane + j*32];
            s  += v[j];
            ss += v[j]*v[j];
        }
        #pragma unroll
        for (int o = 16; o > 0; o >>= 1) {
            s  += __shfl_xor_sync(0xffffffffu, s,  o);
            ss += __shfl_xor_sync(0xffffffffu, ss, o);
        }
        const float mu = s * (1.f/FF);
        const float rs = rsqrtf(ss * (1.f/FF) - mu*mu + EPSF);

        if (!STAGE) {
            size_t ro = ((size_t)(b*(TT+2) + t0 + 1 + row))*FF;
            #pragma unroll
            for (int j = 0; j < 8; ++j) {
                int cch = lane + j*32;
                float w = fmaf((v[j] - mu)*rs, par[256 + cch], par[512 + cch]);
                g_h1[ro + cch] = __float2half(fmaxf(w, 0.f));
            }
        } else {
            float dot = 0.f;
            #pragma unroll
            for (int j = 0; j < 8; ++j) {
                int cch = lane + j*32;
                float w = fmaf((v[j] - mu)*rs, par[256 + cch], par[512 + cch]);
                dot = fmaf(fmaxf(w, 0.f), par[768 + cch], dot);
            }
            #pragma unroll
            for (int o = 16; o > 0; o >>= 1)
                dot += __shfl_xor_sync(0xffffffffu, dot, o);
            if (lane == 0)
                dur_out[b*TT + t0 + row] = fmaxf(dot + lin_b[0], 0.f);
        }
    }
}

// ---------------- gather ----------------
__device__ __forceinline__ void st_cs(float4* p, float4 v) {
    asm volatile("st.global.cs.v4.f32 [%0], {%1,%2,%3,%4};"
                 :: "l"(p), "f"(v.x), "f"(v.y), "f"(v.z), "f"(v.w) : "memory");
}
#define NROWS  (BB*MEL)
#define HROWS  (NROWS/2)
__global__ __launch_bounds__(256)
void gather_k(const float* __restrict__ x, float* __restrict__ out) {
    const long long u  = (long long)blockIdx.x * blockDim.x + threadIdx.x;
    const long long NU = (long long)HROWS * 32;
    if (u >= NU) return;
    const int c8 = (int)(u & 31);
    const long long rowa = u >> 5;
    const long long rowb = rowa + HROWS;
    const int ba = (int)(rowa / MEL);
    const int bb = (int)(rowb / MEL);
    const int ia = __ldg(&g_idx[rowa]);
    const int ib = __ldg(&g_idx[rowb]);
    float4 a0 = make_float4(0.f,0.f,0.f,0.f), a1 = a0, b0 = a0, b1 = a0;
    if (ia >= 0) {
        const float4* s = reinterpret_cast<const float4*>(x) + ((long long)ba*TT + ia)*(DD/4) + c8*2;
        a0 = __ldg(s); a1 = __ldg(s + 1);
    }
    if (ib >= 0) {
        const float4* s = reinterpret_cast<const float4*>(x) + ((long long)bb*TT + ib)*(DD/4) + c8*2;
        b0 = __ldg(s); b1 = __ldg(s + 1);
    }
    float4* da = reinterpret_cast<float4*>(out) + rowa*(DD/4) + c8*2;
    float4* db = reinterpret_cast<float4*>(out) + rowb*(DD/4) + c8*2;
    st_cs(da, a0); st_cs(da + 1, a1);
    st_cs(db, b0); st_cs(db + 1, b1);
}

// ---------------- launch ----------------
extern "C" void kernel_launch(void* const* d_in, const int* in_sizes, int n_in,
                              void* d_out, int out_size) {
    int base = 2;
    if (n_in >= 13 && in_sizes[2] == 1) base = 3;

    const float* x      = (const float*)d_in[0];
    const int*   target = (const int*)  d_in[1];
    const float* c1w = (const float*)d_in[base + 0];
    const float* c1b = (const float*)d_in[base + 1];
    const float* l1g = (const float*)d_in[base + 2];
    const float* l1b = (const float*)d_in[base + 3];
    const float* c2w = (const float*)d_in[base + 4];
    const float* c2b = (const float*)d_in[base + 5];
    const float* l2g = (const float*)d_in[base + 6];
    const float* l2b = (const float*)d_in[base + 7];
    const float* lw  = (const float*)d_in[base + 8];
    const float* lb  = (const float*)d_in[base + 9];

    float* out = (float*)d_out;
    float* dur = out + (size_t)BB * MEL * DD;

    cudaFuncSetAttribute(conv_wmma<0>, cudaFuncAttributeMaxDynamicSharedMemorySize, SMEM_BYTES);
    cudaFuncSetAttribute(conv_wmma<1>, cudaFuncAttributeMaxDynamicSharedMemorySize, SMEM_BYTES);
    cudaFuncSetAttribute(prep_xw,      cudaFuncAttributeMaxDynamicSharedMemorySize, PREP_SMEM);

    const long long NU = (long long)HROWS * 32;
    const int gatherBlocks = (int)((NU + 255)/256);

    cudaStream_t s2 = nullptr;
    cudaEvent_t eFork = nullptr, eJoin = nullptr;
    bool forked = (cudaStreamCreateWithFlags(&s2, cudaStreamNonBlocking) == cudaSuccess)
               && (cudaEventCreateWithFlags(&eFork, cudaEventDisableTiming) == cudaSuccess)
               && (cudaEventCreateWithFlags(&eJoin, cudaEventDisableTiming) == cudaSuccess);

    if (forked) {
        cudaEventRecord(eFork, 0);
        cudaStreamWaitEvent(s2, eFork, 0);
        cum_idx<<<BB, TT, 0, s2>>>(target);
        gather_k<<<gatherBlocks, 256, 0, s2>>>(x, out);
        cudaEventRecord(eJoin, s2);
        prep_xw<<<16 + NXBLK, 512, PREP_SMEM>>>(x, c1w, c2w);
        conv_wmma<0><<<BB*NTILES, TPB, SMEM_BYTES>>>(c1b, l1g, l1b, lw, lb, nullptr);
        conv_wmma<1><<<BB*NTILES, TPB, SMEM_BYTES>>>(c2b, l2g, l2b, lw, lb, dur);
        cudaStreamWaitEvent(0, eJoin, 0);

        cudaEventDestroy(eFork);
        cudaEventDestroy(eJoin);
        cudaStreamDestroy(s2);
    } else {
        if (s2)    cudaStreamDestroy(s2);
        if (eFork) cudaEventDestroy(eFork);
        if (eJoin) cudaEventDestroy(eJoin);

        cum_idx<<<BB, TT>>>(target);
        prep_xw<<<16 + NXBLK, 512, PREP_SMEM>>>(x, c1w, c2w);
        gather_k<<<gatherBlocks, 256>>>(x, out);
        conv_wmma<0><<<BB*NTILES, TPB, SMEM_BYTES>>>(c1b, l1g, l1b, lw, lb, nullptr);
        conv_wmma<1><<<BB*NTILES, TPB, SMEM_BYTES>>>(c2b, l2g, l2b, lw, lb, dur);
    }
}